// round 10
// baseline (speedup 1.0000x reference)
#include <cuda_runtime.h>
#include <cuda_fp16.h>
#include <math.h>

#define BT   4096
#define HID  1024
#define TSEQ 2048
#define KVW  512
#define HD   64

// fp16 scratch (device globals — no allocation allowed)
__device__ __align__(256) half g_xh[(size_t)BT * HID];
__device__ __align__(256) half g_wqh[(size_t)HID * HID];
__device__ __align__(256) half g_wkvh[(size_t)HID * KVW];
__device__ __align__(256) half g_woh[(size_t)HID * HID];
__device__ __align__(256) half g_qh[(size_t)BT * HID];
__device__ __align__(256) half g_kvh[(size_t)BT * KVW];
__device__ __align__(256) half g_atth[(size_t)BT * HID];

// ---------------------------------------------------------------------------
// helpers
// ---------------------------------------------------------------------------
__device__ __forceinline__ unsigned f2h2(float a, float b) {
    half2 h = __float22half2_rn(make_float2(a, b));
    return *(unsigned*)&h;
}
__device__ __forceinline__ void mma16(float* d, const unsigned* a, const unsigned* b) {
    asm volatile(
        "mma.sync.aligned.m16n8k16.row.col.f32.f16.f16.f32 "
        "{%0,%1,%2,%3},{%4,%5,%6,%7},{%8,%9},{%0,%1,%2,%3};\n"
        : "+f"(d[0]), "+f"(d[1]), "+f"(d[2]), "+f"(d[3])
        : "r"(a[0]), "r"(a[1]), "r"(a[2]), "r"(a[3]), "r"(b[0]), "r"(b[1]));
}
__device__ __forceinline__ void ldsm4(unsigned* r, unsigned addr) {
    asm volatile("ldmatrix.sync.aligned.m8n8.x4.shared.b16 {%0,%1,%2,%3}, [%4];"
                 : "=r"(r[0]), "=r"(r[1]), "=r"(r[2]), "=r"(r[3]) : "r"(addr));
}
__device__ __forceinline__ void ldsm2(unsigned* r, unsigned addr) {
    asm volatile("ldmatrix.sync.aligned.m8n8.x2.shared.b16 {%0,%1}, [%2];"
                 : "=r"(r[0]), "=r"(r[1]) : "r"(addr));
}
__device__ __forceinline__ void ldsm2t(unsigned* r, unsigned addr) {
    asm volatile("ldmatrix.sync.aligned.m8n8.x2.trans.shared.b16 {%0,%1}, [%2];"
                 : "=r"(r[0]), "=r"(r[1]) : "r"(addr));
}
__device__ __forceinline__ unsigned sptr(const void* p) {
    return (unsigned)__cvta_generic_to_shared(p);
}
__device__ __forceinline__ void cpa16(unsigned dst, const void* src) {
    asm volatile("cp.async.cg.shared.global [%0], [%1], 16;" :: "r"(dst), "l"(src));
}
__device__ __forceinline__ void cp_commit() {
    asm volatile("cp.async.commit_group;");
}
template<int N> __device__ __forceinline__ void cp_wait() {
    asm volatile("cp.async.wait_group %0;" :: "n"(N));
}

// ---------------------------------------------------------------------------
// fp32 -> fp16 convert
// ---------------------------------------------------------------------------
__global__ __launch_bounds__(256) void conv_f2h(
    const float4* __restrict__ in, uint2* __restrict__ out, int n4)
{
    int i = blockIdx.x * 256 + threadIdx.x;
    if (i < n4) {
        float4 v = in[i];
        out[i] = make_uint2(f2h2(v.x, v.y), f2h2(v.z, v.w));
    }
}

// ---------------------------------------------------------------------------
// fp16 GEMM, cp.async 2-stage. C[M,N] = A[M,K] @ B[K,N].
// BM=128, BN=128, BK=32, 256 thr, 8 warps (2m x 4n), warp tile 64x32.
// ---------------------------------------------------------------------------
#define GAS 40    // sA row stride (halves): 32 + 8 pad (80B rows)
#define GBS 136   // sB row stride (halves): 128 + 8 pad (272B rows)

template<bool HALF_OUT>
__device__ __forceinline__ void gemm_core(
    const half* __restrict__ A, const half* __restrict__ B,
    void* __restrict__ Cv, int m0, int n0, int N, int K,
    half* sA, half* sB)   // sA: 2*128*GAS, sB: 2*32*GBS
{
    const int t = threadIdx.x, lane = t & 31, warp = t >> 5;
    const int wm = warp & 1, wn = warp >> 1;
    const int g = lane >> 2, tig = lane & 3;
    const int KT = K >> 5;

    const int a_row = t >> 2, a_ch = t & 3;   // rows a_row, a_row+64
    const int b_row = t >> 4, b_ch = t & 15;  // rows b_row, b_row+16

    auto issue = [&](int kt, int s) {
        int k0 = kt * 32;
        half* dA = sA + s * 128 * GAS;
        half* dB = sB + s * 32 * GBS;
        #pragma unroll
        for (int u = 0; u < 2; u++) {
            int row = a_row + u * 64;
            cpa16(sptr(&dA[row * GAS + a_ch * 8]),
                  A + (size_t)(m0 + row) * K + k0 + a_ch * 8);
        }
        #pragma unroll
        for (int u = 0; u < 2; u++) {
            int row = b_row + u * 16;
            cpa16(sptr(&dB[row * GBS + b_ch * 8]),
                  B + (size_t)(k0 + row) * N + n0 + b_ch * 8);
        }
        cp_commit();
    };

    float acc[4][4][4] = {};

    issue(0, 0);
    cp_wait<0>();
    __syncthreads();

    for (int kt = 0; kt < KT; kt++) {
        int cur = kt & 1;
        if (kt + 1 < KT) issue(kt + 1, cur ^ 1);

        half* cA = sA + cur * 128 * GAS;
        half* cB = sB + cur * 32 * GBS;

        #pragma unroll
        for (int ks = 0; ks < 2; ks++) {
            unsigned af[4][4];
            #pragma unroll
            for (int mf = 0; mf < 4; mf++) {
                int row = wm * 64 + mf * 16 + (lane & 15);
                int col = ks * 16 + (lane >> 4) * 8;
                ldsm4(af[mf], sptr(&cA[row * GAS + col]));
            }
            #pragma unroll
            for (int nf = 0; nf < 4; nf++) {
                unsigned bf[2];
                ldsm2t(bf, sptr(&cB[(ks * 16 + (lane & 15)) * GBS
                                    + wn * 32 + nf * 8]));
                #pragma unroll
                for (int mf = 0; mf < 4; mf++)
                    mma16(acc[mf][nf], af[mf], bf);
            }
        }

        if (kt + 1 < KT) {
            cp_wait<0>();
            __syncthreads();
        }
    }

    #pragma unroll
    for (int mf = 0; mf < 4; mf++)
        #pragma unroll
        for (int nf = 0; nf < 4; nf++) {
            int r = m0 + wm * 64 + mf * 16 + g;
            int c = n0 + wn * 32 + nf * 8 + tig * 2;
            if (HALF_OUT) {
                half* C = (half*)Cv;
                *(unsigned*)&C[(size_t)r * N + c] =
                    f2h2(acc[mf][nf][0], acc[mf][nf][1]);
                *(unsigned*)&C[(size_t)(r + 8) * N + c] =
                    f2h2(acc[mf][nf][2], acc[mf][nf][3]);
            } else {
                float* C = (float*)Cv;
                *(float2*)(C + (size_t)r * N + c) =
                    make_float2(acc[mf][nf][0], acc[mf][nf][1]);
                *(float2*)(C + (size_t)(r + 8) * N + c) =
                    make_float2(acc[mf][nf][2], acc[mf][nf][3]);
            }
        }
}

// Fused Q + KV projection: blockIdx.x 0..7 -> Wq (N=1024), 8..11 -> Wkv (N=512)
__global__ __launch_bounds__(256) void gemm_qkv(
    const half* __restrict__ x,
    const half* __restrict__ Wq, const half* __restrict__ Wkv,
    half* __restrict__ q, half* __restrict__ kvo)
{
    __shared__ half sA[2 * 128 * GAS];
    __shared__ half sB[2 * 32 * GBS];
    int bx = blockIdx.x;
    if (bx < 8)
        gemm_core<true>(x, Wq, q, blockIdx.y * 128, bx * 128, HID, HID, sA, sB);
    else
        gemm_core<true>(x, Wkv, kvo, blockIdx.y * 128, (bx - 8) * 128, KVW, HID, sA, sB);
}

__global__ __launch_bounds__(256) void gemm_wo(
    const half* __restrict__ A, const half* __restrict__ B,
    float* __restrict__ C)
{
    __shared__ half sA[2 * 128 * GAS];
    __shared__ half sB[2 * 32 * GBS];
    gemm_core<false>(A, B, C, blockIdx.y * 128, blockIdx.x * 128, HID, HID, sA, sB);
}

// ---------------------------------------------------------------------------
// fp16 flash attention, 128-row q-tiles, 8 warps (256 thr), cp.async dbuf KV.
// Grid (T/128, H, B). Warp w owns q-rows [w*16, w*16+16) of the tile.
// ---------------------------------------------------------------------------
#define ASTR 72   // 64 + 8 pad (144B rows)
#define ATT_SMEM ((128 * ASTR + 4 * 64 * ASTR) * 2)   // sQP + sK[2] + sV[2]

__global__ __launch_bounds__(256) void attn_h(
    const half* __restrict__ q, const half* __restrict__ kv,
    half* __restrict__ o)
{
    extern __shared__ half smem[];
    half* sQP = smem;                    // Q (prologue) then P [r][c], 128 rows
    half* sK0 = smem + 128 * ASTR;       // K buffers [c][d]
    half* sV0 = sK0 + 2 * 64 * ASTR;     // V buffers [c][d]

    const int t = threadIdx.x, lane = t & 31, warp = t >> 5;
    const int g = lane >> 2, tig = lane & 3;
    const int Q = gridDim.x - 1 - blockIdx.x;   // long tiles first
    const int h = blockIdx.y, b = blockIdx.z;
    const int kvh = h >> 2;
    const int rb = Q * 128 + warp * 16;         // warp's global row base

    const size_t qbase = (size_t)b * TSEQ * HID + (size_t)h * HD;
    const half* kvp = kv + (size_t)b * TSEQ * KVW + (size_t)kvh * HD;

    const int kv_c = t >> 3, kv_ch = t & 7;   // rows kv_c, kv_c+32

    auto issueKV = [&](int kt, int s) {
        half* dK = sK0 + s * 64 * ASTR;
        half* dV = sV0 + s * 64 * ASTR;
        #pragma unroll
        for (int u = 0; u < 2; u++) {
            int c = kv_c + u * 32;
            const half* rowp = kvp + (size_t)(kt * 64 + c) * KVW;
            cpa16(sptr(&dK[c * ASTR + kv_ch * 8]), rowp + kv_ch * 8);
            cpa16(sptr(&dV[c * ASTR + kv_ch * 8]), rowp + 256 + kv_ch * 8);
        }
        cp_commit();
    };

    issueKV(0, 0);

    // Q tile (pre-scaled by 1/8) -> sQP (128 rows)
    const half2 sc = __float2half2_rn(0.125f);
    #pragma unroll
    for (int u = 0; u < 4; u++) {
        int id = t + 256 * u;
        int r = id >> 3, dq = id & 7;
        uint4 v = *(const uint4*)(q + qbase + (size_t)(Q * 128 + r) * HID + dq * 8);
        half2* hv = (half2*)&v;
        #pragma unroll
        for (int i = 0; i < 4; i++) hv[i] = __hmul2(hv[i], sc);
        *(uint4*)&sQP[r * ASTR + dq * 8] = v;
    }
    cp_wait<0>();
    __syncthreads();

    // Q fragments to registers
    unsigned qa[4][4];
    {
        int row = warp * 16 + (lane & 15);
        int cb = (lane >> 4) * 8;
        #pragma unroll
        for (int ks = 0; ks < 4; ks++)
            ldsm4(qa[ks], sptr(&sQP[row * ASTR + ks * 16 + cb]));
    }
    __syncthreads();   // all warps have Q frags before P overwrites sQP

    float mr0 = -INFINITY, mr1 = -INFINITY, l0 = 0.f, l1 = 0.f;
    float O[8][4] = {};

    const int KTE = 2 * Q + 2;   // k-tiles to process
    for (int kt = 0; kt < KTE; kt++) {
        int cur = kt & 1;
        if (kt + 1 < KTE) issueKV(kt + 1, cur ^ 1);

        half* cK = sK0 + cur * 64 * ASTR;
        half* cV = sV0 + cur * 64 * ASTR;

        // warp fully above diagonal? (all cols > all rows) -> exact no-op
        bool skip = (kt * 64 > rb + 15);

        if (!skip) {
            // S = Q K^T (warp: 16 x 64)
            float s[8][4] = {};
            #pragma unroll
            for (int ks = 0; ks < 4; ks++) {
                #pragma unroll
                for (int nf = 0; nf < 8; nf++) {
                    unsigned bf[2];
                    ldsm2(bf, sptr(&cK[(nf * 8 + (lane & 7)) * ASTR
                                       + ks * 16 + ((lane >> 3) & 1) * 8]));
                    mma16(s[nf], qa[ks], bf);
                }
            }

            // causal mask if this tile can cross the diagonal
            if (kt * 64 + 63 > rb) {
                int r0 = rb + g;
                #pragma unroll
                for (int nf = 0; nf < 8; nf++) {
                    int col = kt * 64 + nf * 8 + tig * 2;
                    if (col     > r0)     s[nf][0] = -INFINITY;
                    if (col + 1 > r0)     s[nf][1] = -INFINITY;
                    if (col     > r0 + 8) s[nf][2] = -INFINITY;
                    if (col + 1 > r0 + 8) s[nf][3] = -INFINITY;
                }
            }

            // online softmax
            float mx0 = -INFINITY, mx1 = -INFINITY;
            #pragma unroll
            for (int nf = 0; nf < 8; nf++) {
                mx0 = fmaxf(mx0, fmaxf(s[nf][0], s[nf][1]));
                mx1 = fmaxf(mx1, fmaxf(s[nf][2], s[nf][3]));
            }
            #pragma unroll
            for (int off = 1; off < 4; off <<= 1) {
                mx0 = fmaxf(mx0, __shfl_xor_sync(0xffffffffu, mx0, off));
                mx1 = fmaxf(mx1, __shfl_xor_sync(0xffffffffu, mx1, off));
            }
            float nm0 = fmaxf(mr0, mx0), nm1 = fmaxf(mr1, mx1);
            float a0 = __expf(mr0 - nm0), a1 = __expf(mr1 - nm1);
            float rs0 = 0.f, rs1 = 0.f;
            #pragma unroll
            for (int nf = 0; nf < 8; nf++) {
                s[nf][0] = __expf(s[nf][0] - nm0);
                s[nf][1] = __expf(s[nf][1] - nm0);
                s[nf][2] = __expf(s[nf][2] - nm1);
                s[nf][3] = __expf(s[nf][3] - nm1);
                rs0 += s[nf][0] + s[nf][1];
                rs1 += s[nf][2] + s[nf][3];
            }
            #pragma unroll
            for (int off = 1; off < 4; off <<= 1) {
                rs0 += __shfl_xor_sync(0xffffffffu, rs0, off);
                rs1 += __shfl_xor_sync(0xffffffffu, rs1, off);
            }
            l0 = l0 * a0 + rs0;  l1 = l1 * a1 + rs1;
            mr0 = nm0;           mr1 = nm1;
            #pragma unroll
            for (int df = 0; df < 8; df++) {
                O[df][0] *= a0; O[df][1] *= a0;
                O[df][2] *= a1; O[df][3] *= a1;
            }

            // P -> sQP (warp-private rows)
            {
                int r = warp * 16 + g;
                #pragma unroll
                for (int nf = 0; nf < 8; nf++) {
                    int c = nf * 8 + tig * 2;
                    *(unsigned*)&sQP[r * ASTR + c]       = f2h2(s[nf][0], s[nf][1]);
                    *(unsigned*)&sQP[(r + 8) * ASTR + c] = f2h2(s[nf][2], s[nf][3]);
                }
            }
            __syncwarp();

            // O += P @ V
            #pragma unroll
            for (int ks = 0; ks < 4; ks++) {
                unsigned pa[4];
                int row = warp * 16 + (lane & 15);
                int cb = ks * 16 + (lane >> 4) * 8;
                ldsm4(pa, sptr(&sQP[row * ASTR + cb]));
                #pragma unroll
                for (int df = 0; df < 8; df++) {
                    unsigned bf[2];
                    ldsm2t(bf, sptr(&cV[(ks * 16 + (lane & 15)) * ASTR + df * 8]));
                    mma16(O[df], pa, bf);
                }
            }
        }

        if (kt + 1 < KTE) {
            cp_wait<0>();
            __syncthreads();
        }
    }

    // epilogue: half output for Wo GEMM
    float inv0 = 1.f / l0, inv1 = 1.f / l1;
    int r = rb + g;
    #pragma unroll
    for (int df = 0; df < 8; df++) {
        int c = h * HD + df * 8 + tig * 2;
        *(unsigned*)&o[(size_t)(b * TSEQ + r) * HID + c] =
            f2h2(O[df][0] * inv0, O[df][1] * inv0);
        *(unsigned*)&o[(size_t)(b * TSEQ + r + 8) * HID + c] =
            f2h2(O[df][2] * inv1, O[df][3] * inv1);
    }
}

// ---------------------------------------------------------------------------
extern "C" void kernel_launch(void* const* d_in, const int* in_sizes, int n_in,
                              void* d_out, int out_size)
{
    const float* x   = (const float*)d_in[0];
    const float* Wq  = (const float*)d_in[1];
    const float* Wkv = (const float*)d_in[2];
    const float* Wo  = (const float*)d_in[3];
    float* out = (float*)d_out;

    half *xh, *wqh, *wkvh, *woh, *qh, *kvh, *atth;
    cudaGetSymbolAddress((void**)&xh,   g_xh);
    cudaGetSymbolAddress((void**)&wqh,  g_wqh);
    cudaGetSymbolAddress((void**)&wkvh, g_wkvh);
    cudaGetSymbolAddress((void**)&woh,  g_woh);
    cudaGetSymbolAddress((void**)&qh,   g_qh);
    cudaGetSymbolAddress((void**)&kvh,  g_kvh);
    cudaGetSymbolAddress((void**)&atth, g_atth);

    cudaFuncSetAttribute(attn_h,
                         cudaFuncAttributeMaxDynamicSharedMemorySize, ATT_SMEM);

    int nx = BT * HID / 4, nq = HID * HID / 4, nk = HID * KVW / 4;
    conv_f2h<<<(nx + 255) / 256, 256>>>((const float4*)x,   (uint2*)xh,   nx);
    conv_f2h<<<(nq + 255) / 256, 256>>>((const float4*)Wq,  (uint2*)wqh,  nq);
    conv_f2h<<<(nk + 255) / 256, 256>>>((const float4*)Wkv, (uint2*)wkvh, nk);
    conv_f2h<<<(nq + 255) / 256, 256>>>((const float4*)Wo,  (uint2*)woh,  nq);

    gemm_qkv<<<dim3(12, BT / 128), 256>>>(xh, wqh, wkvh, qh, kvh);
    attn_h<<<dim3(TSEQ / 128, 16, 2), 256, ATT_SMEM>>>(qh, kvh, atth);
    gemm_wo<<<dim3(HID / 128, BT / 128), 256>>>(atth, woh, out);
}

// round 11
// speedup vs baseline: 1.0266x; 1.0266x over previous
#include <cuda_runtime.h>
#include <cuda_fp16.h>
#include <math.h>

#define BT   4096
#define HID  1024
#define TSEQ 2048
#define KVW  512
#define HD   64

// fp16 scratch (device globals — no allocation allowed)
__device__ __align__(256) half g_xh[(size_t)BT * HID];
__device__ __align__(256) half g_wqh[(size_t)HID * HID];
__device__ __align__(256) half g_wkvh[(size_t)HID * KVW];
__device__ __align__(256) half g_woh[(size_t)HID * HID];
__device__ __align__(256) half g_qh[(size_t)BT * HID];
__device__ __align__(256) half g_kvh[(size_t)BT * KVW];
__device__ __align__(256) half g_atth[(size_t)BT * HID];

// ---------------------------------------------------------------------------
// helpers
// ---------------------------------------------------------------------------
__device__ __forceinline__ unsigned f2h2(float a, float b) {
    half2 h = __float22half2_rn(make_float2(a, b));
    return *(unsigned*)&h;
}
__device__ __forceinline__ void mma16(float* d, const unsigned* a, const unsigned* b) {
    asm volatile(
        "mma.sync.aligned.m16n8k16.row.col.f32.f16.f16.f32 "
        "{%0,%1,%2,%3},{%4,%5,%6,%7},{%8,%9},{%0,%1,%2,%3};\n"
        : "+f"(d[0]), "+f"(d[1]), "+f"(d[2]), "+f"(d[3])
        : "r"(a[0]), "r"(a[1]), "r"(a[2]), "r"(a[3]), "r"(b[0]), "r"(b[1]));
}
__device__ __forceinline__ void ldsm4(unsigned* r, unsigned addr) {
    asm volatile("ldmatrix.sync.aligned.m8n8.x4.shared.b16 {%0,%1,%2,%3}, [%4];"
                 : "=r"(r[0]), "=r"(r[1]), "=r"(r[2]), "=r"(r[3]) : "r"(addr));
}
__device__ __forceinline__ void ldsm2(unsigned* r, unsigned addr) {
    asm volatile("ldmatrix.sync.aligned.m8n8.x2.shared.b16 {%0,%1}, [%2];"
                 : "=r"(r[0]), "=r"(r[1]) : "r"(addr));
}
__device__ __forceinline__ void ldsm2t(unsigned* r, unsigned addr) {
    asm volatile("ldmatrix.sync.aligned.m8n8.x2.trans.shared.b16 {%0,%1}, [%2];"
                 : "=r"(r[0]), "=r"(r[1]) : "r"(addr));
}
__device__ __forceinline__ unsigned sptr(const void* p) {
    return (unsigned)__cvta_generic_to_shared(p);
}
__device__ __forceinline__ void cpa16(unsigned dst, const void* src) {
    asm volatile("cp.async.cg.shared.global [%0], [%1], 16;" :: "r"(dst), "l"(src));
}
__device__ __forceinline__ void cp_commit() {
    asm volatile("cp.async.commit_group;");
}
template<int N> __device__ __forceinline__ void cp_wait() {
    asm volatile("cp.async.wait_group %0;" :: "n"(N));
}

// ---------------------------------------------------------------------------
// fused fp32 -> fp16 convert for all 4 tensors (one launch)
// ---------------------------------------------------------------------------
#define CN0 (BT * HID / 4)     // x     : 1048576 float4
#define CN1 (HID * HID / 4)    // Wq    :  262144
#define CN2 (HID * KVW / 4)    // Wkv   :  131072
#define CN3 (HID * HID / 4)    // Wo    :  262144
#define CNT (CN0 + CN1 + CN2 + CN3)

__global__ __launch_bounds__(256) void conv_all(
    const float4* __restrict__ x,  const float4* __restrict__ wq,
    const float4* __restrict__ wkv, const float4* __restrict__ wo,
    uint2* __restrict__ xh, uint2* __restrict__ wqh,
    uint2* __restrict__ wkvh, uint2* __restrict__ woh)
{
    int i = blockIdx.x * 256 + threadIdx.x;
    const float4* src;
    uint2* dst;
    int j;
    if (i < CN0)                  { src = x;   dst = xh;   j = i; }
    else if (i < CN0 + CN1)       { src = wq;  dst = wqh;  j = i - CN0; }
    else if (i < CN0 + CN1 + CN2) { src = wkv; dst = wkvh; j = i - CN0 - CN1; }
    else if (i < CNT)             { src = wo;  dst = woh;  j = i - CN0 - CN1 - CN2; }
    else return;
    float4 v = src[j];
    dst[j] = make_uint2(f2h2(v.x, v.y), f2h2(v.z, v.w));
}

// ---------------------------------------------------------------------------
// fp16 GEMM, cp.async 3-stage (R8 measured-best config).
// C[M,N] = A[M,K] @ B[K,N]. BM=128, BN=64, BK=32, 256 thr, 8 warps (4m x 2n).
// ---------------------------------------------------------------------------
#define GAS 40   // sA row stride (halves): 32 + 8 pad (80B rows)
#define GBS 72   // sB row stride (halves): 64 + 8 pad (144B rows)

template<bool HALF_OUT>
__device__ __forceinline__ void gemm_core(
    const half* __restrict__ A, const half* __restrict__ B,
    void* __restrict__ Cv, int m0, int n0, int N, int K,
    half* sA, half* sB)   // sA: 3*128*GAS, sB: 3*32*GBS
{
    const int t = threadIdx.x, lane = t & 31, warp = t >> 5;
    const int wm = warp & 3, wn = warp >> 2;
    const int g = lane >> 2, tig = lane & 3;
    const int KT = K >> 5;

    const int a_row = t >> 2, a_ch = t & 3;       // 2 chunks/thread
    const int b_row = t >> 3, b_ch = t & 7;       // 1 chunk/thread

    auto issue = [&](int kt, int s) {
        int k0 = kt * 32;
        half* dA = sA + s * 128 * GAS;
        half* dB = sB + s * 32 * GBS;
        #pragma unroll
        for (int u = 0; u < 2; u++) {
            int row = a_row + u * 64;
            cpa16(sptr(&dA[row * GAS + a_ch * 8]),
                  A + (size_t)(m0 + row) * K + k0 + a_ch * 8);
        }
        cpa16(sptr(&dB[b_row * GBS + b_ch * 8]),
              B + (size_t)(k0 + b_row) * N + n0 + b_ch * 8);
        cp_commit();
    };

    float acc[2][4][4] = {};

    issue(0, 0);
    issue(1, 1);
    cp_wait<1>();
    __syncthreads();

    for (int kt = 0; kt < KT; kt++) {
        int cur = kt % 3;
        if (kt + 2 < KT) issue(kt + 2, (kt + 2) % 3);

        half* cA = sA + cur * 128 * GAS;
        half* cB = sB + cur * 32 * GBS;

        #pragma unroll
        for (int ks = 0; ks < 2; ks++) {
            unsigned af[2][4];
            #pragma unroll
            for (int mf = 0; mf < 2; mf++) {
                int row = wm * 32 + mf * 16 + (lane & 15);
                int col = ks * 16 + (lane >> 4) * 8;
                ldsm4(af[mf], sptr(&cA[row * GAS + col]));
            }
            #pragma unroll
            for (int nf = 0; nf < 4; nf++) {
                unsigned bf[2];
                ldsm2t(bf, sptr(&cB[(ks * 16 + (lane & 15)) * GBS
                                    + wn * 32 + nf * 8]));
                #pragma unroll
                for (int mf = 0; mf < 2; mf++)
                    mma16(acc[mf][nf], af[mf], bf);
            }
        }

        if (kt + 1 < KT) {
            if (kt + 2 < KT) cp_wait<1>(); else cp_wait<0>();
            __syncthreads();
        }
    }

    #pragma unroll
    for (int mf = 0; mf < 2; mf++)
        #pragma unroll
        for (int nf = 0; nf < 4; nf++) {
            int r = m0 + wm * 32 + mf * 16 + g;
            int c = n0 + wn * 32 + nf * 8 + tig * 2;
            if (HALF_OUT) {
                half* C = (half*)Cv;
                *(unsigned*)&C[(size_t)r * N + c] =
                    f2h2(acc[mf][nf][0], acc[mf][nf][1]);
                *(unsigned*)&C[(size_t)(r + 8) * N + c] =
                    f2h2(acc[mf][nf][2], acc[mf][nf][3]);
            } else {
                float* C = (float*)Cv;
                *(float2*)(C + (size_t)r * N + c) =
                    make_float2(acc[mf][nf][0], acc[mf][nf][1]);
                *(float2*)(C + (size_t)(r + 8) * N + c) =
                    make_float2(acc[mf][nf][2], acc[mf][nf][3]);
            }
        }
}

// Fused Q + KV projection: blockIdx.x 0..15 -> Wq, 16..23 -> Wkv. half out.
__global__ __launch_bounds__(256) void gemm_qkv(
    const half* __restrict__ x,
    const half* __restrict__ Wq, const half* __restrict__ Wkv,
    half* __restrict__ q, half* __restrict__ kvo)
{
    __shared__ half sA[3 * 128 * GAS];
    __shared__ half sB[3 * 32 * GBS];
    int bx = blockIdx.x;
    if (bx < 16)
        gemm_core<true>(x, Wq, q, blockIdx.y * 128, bx * 64, HID, HID, sA, sB);
    else
        gemm_core<true>(x, Wkv, kvo, blockIdx.y * 128, (bx - 16) * 64, KVW, HID, sA, sB);
}

__global__ __launch_bounds__(256) void gemm_wo(
    const half* __restrict__ A, const half* __restrict__ B,
    float* __restrict__ C)
{
    __shared__ half sA[3 * 128 * GAS];
    __shared__ half sB[3 * 32 * GBS];
    gemm_core<false>(A, B, C, blockIdx.y * 128, blockIdx.x * 64, HID, HID, sA, sB);
}

// ---------------------------------------------------------------------------
// fp16 flash attention, 128-row q-tiles, 8 warps (256 thr), cp.async dbuf KV.
// Grid (T/128, H, B). Warp w owns q-rows [w*16, w*16+16) of the tile.
// ---------------------------------------------------------------------------
#define ASTR 72   // 64 + 8 pad (144B rows)
#define ATT_SMEM ((128 * ASTR + 4 * 64 * ASTR) * 2)   // sQP + sK[2] + sV[2]

__global__ __launch_bounds__(256) void attn_h(
    const half* __restrict__ q, const half* __restrict__ kv,
    half* __restrict__ o)
{
    extern __shared__ half smem[];
    half* sQP = smem;                    // Q (prologue) then P [r][c], 128 rows
    half* sK0 = smem + 128 * ASTR;       // K buffers [c][d]
    half* sV0 = sK0 + 2 * 64 * ASTR;     // V buffers [c][d]

    const int t = threadIdx.x, lane = t & 31, warp = t >> 5;
    const int g = lane >> 2, tig = lane & 3;
    const int Q = gridDim.x - 1 - blockIdx.x;   // long tiles first
    const int h = blockIdx.y, b = blockIdx.z;
    const int kvh = h >> 2;
    const int rb = Q * 128 + warp * 16;         // warp's global row base

    const size_t qbase = (size_t)b * TSEQ * HID + (size_t)h * HD;
    const half* kvp = kv + (size_t)b * TSEQ * KVW + (size_t)kvh * HD;

    const int kv_c = t >> 3, kv_ch = t & 7;   // rows kv_c, kv_c+32

    auto issueKV = [&](int kt, int s) {
        half* dK = sK0 + s * 64 * ASTR;
        half* dV = sV0 + s * 64 * ASTR;
        #pragma unroll
        for (int u = 0; u < 2; u++) {
            int c = kv_c + u * 32;
            const half* rowp = kvp + (size_t)(kt * 64 + c) * KVW;
            cpa16(sptr(&dK[c * ASTR + kv_ch * 8]), rowp + kv_ch * 8);
            cpa16(sptr(&dV[c * ASTR + kv_ch * 8]), rowp + 256 + kv_ch * 8);
        }
        cp_commit();
    };

    issueKV(0, 0);

    // Q tile (pre-scaled by 1/8) -> sQP (128 rows)
    const half2 sc = __float2half2_rn(0.125f);
    #pragma unroll
    for (int u = 0; u < 4; u++) {
        int id = t + 256 * u;
        int r = id >> 3, dq = id & 7;
        uint4 v = *(const uint4*)(q + qbase + (size_t)(Q * 128 + r) * HID + dq * 8);
        half2* hv = (half2*)&v;
        #pragma unroll
        for (int i = 0; i < 4; i++) hv[i] = __hmul2(hv[i], sc);
        *(uint4*)&sQP[r * ASTR + dq * 8] = v;
    }
    cp_wait<0>();
    __syncthreads();

    // Q fragments to registers
    unsigned qa[4][4];
    {
        int row = warp * 16 + (lane & 15);
        int cb = (lane >> 4) * 8;
        #pragma unroll
        for (int ks = 0; ks < 4; ks++)
            ldsm4(qa[ks], sptr(&sQP[row * ASTR + ks * 16 + cb]));
    }
    __syncthreads();   // all warps have Q frags before P overwrites sQP

    float mr0 = -INFINITY, mr1 = -INFINITY, l0 = 0.f, l1 = 0.f;
    float O[8][4] = {};

    const int KTE = 2 * Q + 2;   // k-tiles to process
    for (int kt = 0; kt < KTE; kt++) {
        int cur = kt & 1;
        if (kt + 1 < KTE) issueKV(kt + 1, cur ^ 1);

        half* cK = sK0 + cur * 64 * ASTR;
        half* cV = sV0 + cur * 64 * ASTR;

        // warp fully above diagonal? (all cols > all rows) -> exact no-op
        bool skip = (kt * 64 > rb + 15);

        if (!skip) {
            // S = Q K^T (warp: 16 x 64)
            float s[8][4] = {};
            #pragma unroll
            for (int ks = 0; ks < 4; ks++) {
                #pragma unroll
                for (int nf = 0; nf < 8; nf++) {
                    unsigned bf[2];
                    ldsm2(bf, sptr(&cK[(nf * 8 + (lane & 7)) * ASTR
                                       + ks * 16 + ((lane >> 3) & 1) * 8]));
                    mma16(s[nf], qa[ks], bf);
                }
            }

            // causal mask if this tile can cross the diagonal
            if (kt * 64 + 63 > rb) {
                int r0 = rb + g;
                #pragma unroll
                for (int nf = 0; nf < 8; nf++) {
                    int col = kt * 64 + nf * 8 + tig * 2;
                    if (col     > r0)     s[nf][0] = -INFINITY;
                    if (col + 1 > r0)     s[nf][1] = -INFINITY;
                    if (col     > r0 + 8) s[nf][2] = -INFINITY;
                    if (col + 1 > r0 + 8) s[nf][3] = -INFINITY;
                }
            }

            // online softmax
            float mx0 = -INFINITY, mx1 = -INFINITY;
            #pragma unroll
            for (int nf = 0; nf < 8; nf++) {
                mx0 = fmaxf(mx0, fmaxf(s[nf][0], s[nf][1]));
                mx1 = fmaxf(mx1, fmaxf(s[nf][2], s[nf][3]));
            }
            #pragma unroll
            for (int off = 1; off < 4; off <<= 1) {
                mx0 = fmaxf(mx0, __shfl_xor_sync(0xffffffffu, mx0, off));
                mx1 = fmaxf(mx1, __shfl_xor_sync(0xffffffffu, mx1, off));
            }
            float nm0 = fmaxf(mr0, mx0), nm1 = fmaxf(mr1, mx1);
            float a0 = __expf(mr0 - nm0), a1 = __expf(mr1 - nm1);
            float rs0 = 0.f, rs1 = 0.f;
            #pragma unroll
            for (int nf = 0; nf < 8; nf++) {
                s[nf][0] = __expf(s[nf][0] - nm0);
                s[nf][1] = __expf(s[nf][1] - nm0);
                s[nf][2] = __expf(s[nf][2] - nm1);
                s[nf][3] = __expf(s[nf][3] - nm1);
                rs0 += s[nf][0] + s[nf][1];
                rs1 += s[nf][2] + s[nf][3];
            }
            #pragma unroll
            for (int off = 1; off < 4; off <<= 1) {
                rs0 += __shfl_xor_sync(0xffffffffu, rs0, off);
                rs1 += __shfl_xor_sync(0xffffffffu, rs1, off);
            }
            l0 = l0 * a0 + rs0;  l1 = l1 * a1 + rs1;
            mr0 = nm0;           mr1 = nm1;
            #pragma unroll
            for (int df = 0; df < 8; df++) {
                O[df][0] *= a0; O[df][1] *= a0;
                O[df][2] *= a1; O[df][3] *= a1;
            }

            // P -> sQP (warp-private rows)
            {
                int r = warp * 16 + g;
                #pragma unroll
                for (int nf = 0; nf < 8; nf++) {
                    int c = nf * 8 + tig * 2;
                    *(unsigned*)&sQP[r * ASTR + c]       = f2h2(s[nf][0], s[nf][1]);
                    *(unsigned*)&sQP[(r + 8) * ASTR + c] = f2h2(s[nf][2], s[nf][3]);
                }
            }
            __syncwarp();

            // O += P @ V
            #pragma unroll
            for (int ks = 0; ks < 4; ks++) {
                unsigned pa[4];
                int row = warp * 16 + (lane & 15);
                int cb = ks * 16 + (lane >> 4) * 8;
                ldsm4(pa, sptr(&sQP[row * ASTR + cb]));
                #pragma unroll
                for (int df = 0; df < 8; df++) {
                    unsigned bf[2];
                    ldsm2t(bf, sptr(&cV[(ks * 16 + (lane & 15)) * ASTR + df * 8]));
                    mma16(O[df], pa, bf);
                }
            }
        }

        if (kt + 1 < KTE) {
            cp_wait<0>();
            __syncthreads();
        }
    }

    // epilogue: half output for Wo GEMM
    float inv0 = 1.f / l0, inv1 = 1.f / l1;
    int r = rb + g;
    #pragma unroll
    for (int df = 0; df < 8; df++) {
        int c = h * HD + df * 8 + tig * 2;
        *(unsigned*)&o[(size_t)(b * TSEQ + r) * HID + c] =
            f2h2(O[df][0] * inv0, O[df][1] * inv0);
        *(unsigned*)&o[(size_t)(b * TSEQ + r + 8) * HID + c] =
            f2h2(O[df][2] * inv1, O[df][3] * inv1);
    }
}

// ---------------------------------------------------------------------------
extern "C" void kernel_launch(void* const* d_in, const int* in_sizes, int n_in,
                              void* d_out, int out_size)
{
    const float* x   = (const float*)d_in[0];
    const float* Wq  = (const float*)d_in[1];
    const float* Wkv = (const float*)d_in[2];
    const float* Wo  = (const float*)d_in[3];
    float* out = (float*)d_out;

    half *xh, *wqh, *wkvh, *woh, *qh, *kvh, *atth;
    cudaGetSymbolAddress((void**)&xh,   g_xh);
    cudaGetSymbolAddress((void**)&wqh,  g_wqh);
    cudaGetSymbolAddress((void**)&wkvh, g_wkvh);
    cudaGetSymbolAddress((void**)&woh,  g_woh);
    cudaGetSymbolAddress((void**)&qh,   g_qh);
    cudaGetSymbolAddress((void**)&kvh,  g_kvh);
    cudaGetSymbolAddress((void**)&atth, g_atth);

    cudaFuncSetAttribute(attn_h,
                         cudaFuncAttributeMaxDynamicSharedMemorySize, ATT_SMEM);

    conv_all<<<(CNT + 255) / 256, 256>>>(
        (const float4*)x, (const float4*)Wq, (const float4*)Wkv, (const float4*)Wo,
        (uint2*)xh, (uint2*)wqh, (uint2*)wkvh, (uint2*)woh);

    gemm_qkv<<<dim3(24, BT / 128), 256>>>(xh, wqh, wkvh, qh, kvh);
    attn_h<<<dim3(TSEQ / 128, 16, 2), 256, ATT_SMEM>>>(qh, kvh, atth);
    gemm_wo<<<dim3(HID / 64, BT / 128), 256>>>(atth, woh, out);
}

// round 12
// speedup vs baseline: 1.1083x; 1.0795x over previous
#include <cuda_runtime.h>
#include <cuda_fp16.h>
#include <math.h>

#define BT   4096
#define HID  1024
#define TSEQ 2048
#define KVW  512
#define HD   64

// fp16 scratch (device globals — no allocation allowed)
__device__ __align__(256) half g_xh[(size_t)BT * HID];
__device__ __align__(256) half g_wqh[(size_t)HID * HID];
__device__ __align__(256) half g_wkvh[(size_t)HID * KVW];
__device__ __align__(256) half g_woh[(size_t)HID * HID];
__device__ __align__(256) half g_qh[(size_t)BT * HID];
__device__ __align__(256) half g_kvh[(size_t)BT * KVW];
__device__ __align__(256) half g_atth[(size_t)BT * HID];

// ---------------------------------------------------------------------------
// helpers
// ---------------------------------------------------------------------------
__device__ __forceinline__ unsigned f2h2(float a, float b) {
    half2 h = __float22half2_rn(make_float2(a, b));
    return *(unsigned*)&h;
}
__device__ __forceinline__ void mma16(float* d, const unsigned* a, const unsigned* b) {
    asm volatile(
        "mma.sync.aligned.m16n8k16.row.col.f32.f16.f16.f32 "
        "{%0,%1,%2,%3},{%4,%5,%6,%7},{%8,%9},{%0,%1,%2,%3};\n"
        : "+f"(d[0]), "+f"(d[1]), "+f"(d[2]), "+f"(d[3])
        : "r"(a[0]), "r"(a[1]), "r"(a[2]), "r"(a[3]), "r"(b[0]), "r"(b[1]));
}
__device__ __forceinline__ void ldsm4(unsigned* r, unsigned addr) {
    asm volatile("ldmatrix.sync.aligned.m8n8.x4.shared.b16 {%0,%1,%2,%3}, [%4];"
                 : "=r"(r[0]), "=r"(r[1]), "=r"(r[2]), "=r"(r[3]) : "r"(addr));
}
__device__ __forceinline__ void ldsm2(unsigned* r, unsigned addr) {
    asm volatile("ldmatrix.sync.aligned.m8n8.x2.shared.b16 {%0,%1}, [%2];"
                 : "=r"(r[0]), "=r"(r[1]) : "r"(addr));
}
__device__ __forceinline__ void ldsm2t(unsigned* r, unsigned addr) {
    asm volatile("ldmatrix.sync.aligned.m8n8.x2.trans.shared.b16 {%0,%1}, [%2];"
                 : "=r"(r[0]), "=r"(r[1]) : "r"(addr));
}
__device__ __forceinline__ unsigned sptr(const void* p) {
    return (unsigned)__cvta_generic_to_shared(p);
}
__device__ __forceinline__ void cpa16(unsigned dst, const void* src) {
    asm volatile("cp.async.cg.shared.global [%0], [%1], 16;" :: "r"(dst), "l"(src));
}
__device__ __forceinline__ void cp_commit() {
    asm volatile("cp.async.commit_group;");
}
template<int N> __device__ __forceinline__ void cp_wait() {
    asm volatile("cp.async.wait_group %0;" :: "n"(N));
}

// ---------------------------------------------------------------------------
// fused fp32 -> fp16 convert for all 4 tensors (one launch)
// ---------------------------------------------------------------------------
#define CN0 (BT * HID / 4)     // x
#define CN1 (HID * HID / 4)    // Wq
#define CN2 (HID * KVW / 4)    // Wkv
#define CN3 (HID * HID / 4)    // Wo
#define CNT (CN0 + CN1 + CN2 + CN3)

__global__ __launch_bounds__(256) void conv_all(
    const float4* __restrict__ x,  const float4* __restrict__ wq,
    const float4* __restrict__ wkv, const float4* __restrict__ wo,
    uint2* __restrict__ xh, uint2* __restrict__ wqh,
    uint2* __restrict__ wkvh, uint2* __restrict__ woh)
{
    int i = blockIdx.x * 256 + threadIdx.x;
    const float4* src;
    uint2* dst;
    int j;
    if (i < CN0)                  { src = x;   dst = xh;   j = i; }
    else if (i < CN0 + CN1)       { src = wq;  dst = wqh;  j = i - CN0; }
    else if (i < CN0 + CN1 + CN2) { src = wkv; dst = wkvh; j = i - CN0 - CN1; }
    else if (i < CNT)             { src = wo;  dst = woh;  j = i - CN0 - CN1 - CN2; }
    else return;
    float4 v = src[j];
    dst[j] = make_uint2(f2h2(v.x, v.y), f2h2(v.z, v.w));
}

// ---------------------------------------------------------------------------
// fp16 GEMM, cp.async 3-stage (R8 measured-best config).
// C[M,N] = A[M,K] @ B[K,N]. BM=128, BN=64, BK=32, 256 thr, 8 warps (4m x 2n).
// ---------------------------------------------------------------------------
#define GAS 40   // sA row stride (halves): 32 + 8 pad
#define GBS 72   // sB row stride (halves): 64 + 8 pad

template<bool HALF_OUT>
__device__ __forceinline__ void gemm_core(
    const half* __restrict__ A, const half* __restrict__ B,
    void* __restrict__ Cv, int m0, int n0, int N, int K,
    half* sA, half* sB)
{
    const int t = threadIdx.x, lane = t & 31, warp = t >> 5;
    const int wm = warp & 3, wn = warp >> 2;
    const int g = lane >> 2, tig = lane & 3;
    const int KT = K >> 5;

    const int a_row = t >> 2, a_ch = t & 3;
    const int b_row = t >> 3, b_ch = t & 7;

    auto issue = [&](int kt, int s) {
        int k0 = kt * 32;
        half* dA = sA + s * 128 * GAS;
        half* dB = sB + s * 32 * GBS;
        #pragma unroll
        for (int u = 0; u < 2; u++) {
            int row = a_row + u * 64;
            cpa16(sptr(&dA[row * GAS + a_ch * 8]),
                  A + (size_t)(m0 + row) * K + k0 + a_ch * 8);
        }
        cpa16(sptr(&dB[b_row * GBS + b_ch * 8]),
              B + (size_t)(k0 + b_row) * N + n0 + b_ch * 8);
        cp_commit();
    };

    float acc[2][4][4] = {};

    issue(0, 0);
    issue(1, 1);
    cp_wait<1>();
    __syncthreads();

    for (int kt = 0; kt < KT; kt++) {
        int cur = kt % 3;
        if (kt + 2 < KT) issue(kt + 2, (kt + 2) % 3);

        half* cA = sA + cur * 128 * GAS;
        half* cB = sB + cur * 32 * GBS;

        #pragma unroll
        for (int ks = 0; ks < 2; ks++) {
            unsigned af[2][4];
            #pragma unroll
            for (int mf = 0; mf < 2; mf++) {
                int row = wm * 32 + mf * 16 + (lane & 15);
                int col = ks * 16 + (lane >> 4) * 8;
                ldsm4(af[mf], sptr(&cA[row * GAS + col]));
            }
            #pragma unroll
            for (int nf = 0; nf < 4; nf++) {
                unsigned bf[2];
                ldsm2t(bf, sptr(&cB[(ks * 16 + (lane & 15)) * GBS
                                    + wn * 32 + nf * 8]));
                #pragma unroll
                for (int mf = 0; mf < 2; mf++)
                    mma16(acc[mf][nf], af[mf], bf);
            }
        }

        if (kt + 1 < KT) {
            if (kt + 2 < KT) cp_wait<1>(); else cp_wait<0>();
            __syncthreads();
        }
    }

    #pragma unroll
    for (int mf = 0; mf < 2; mf++)
        #pragma unroll
        for (int nf = 0; nf < 4; nf++) {
            int r = m0 + wm * 32 + mf * 16 + g;
            int c = n0 + wn * 32 + nf * 8 + tig * 2;
            if (HALF_OUT) {
                half* C = (half*)Cv;
                *(unsigned*)&C[(size_t)r * N + c] =
                    f2h2(acc[mf][nf][0], acc[mf][nf][1]);
                *(unsigned*)&C[(size_t)(r + 8) * N + c] =
                    f2h2(acc[mf][nf][2], acc[mf][nf][3]);
            } else {
                float* C = (float*)Cv;
                *(float2*)(C + (size_t)r * N + c) =
                    make_float2(acc[mf][nf][0], acc[mf][nf][1]);
                *(float2*)(C + (size_t)(r + 8) * N + c) =
                    make_float2(acc[mf][nf][2], acc[mf][nf][3]);
            }
        }
}

// Fused Q + KV projection: blockIdx.x 0..15 -> Wq, 16..23 -> Wkv. half out.
__global__ __launch_bounds__(256) void gemm_qkv(
    const half* __restrict__ x,
    const half* __restrict__ Wq, const half* __restrict__ Wkv,
    half* __restrict__ q, half* __restrict__ kvo)
{
    __shared__ half sA[3 * 128 * GAS];
    __shared__ half sB[3 * 32 * GBS];
    int bx = blockIdx.x;
    if (bx < 16)
        gemm_core<true>(x, Wq, q, blockIdx.y * 128, bx * 64, HID, HID, sA, sB);
    else
        gemm_core<true>(x, Wkv, kvo, blockIdx.y * 128, (bx - 16) * 64, KVW, HID, sA, sB);
}

__global__ __launch_bounds__(256) void gemm_wo(
    const half* __restrict__ A, const half* __restrict__ B,
    float* __restrict__ C)
{
    __shared__ half sA[3 * 128 * GAS];
    __shared__ half sB[3 * 32 * GBS];
    gemm_core<false>(A, B, C, blockIdx.y * 128, blockIdx.x * 64, HID, HID, sA, sB);
}

// ---------------------------------------------------------------------------
// fp16 flash attention (R8 measured-best config): 64-row q-tiles, 128 threads
// (4 warps), cp.async double-buffered K/V. Grid (T/64, H, B).
// Warp w owns q-rows [w*16, w*16+16). Q frags in registers, sQP reused for P.
// ---------------------------------------------------------------------------
#define ASTR 72   // 64 + 8 pad (144B rows)

__global__ __launch_bounds__(128) void attn_h(
    const half* __restrict__ q, const half* __restrict__ kv,
    half* __restrict__ o)
{
    __shared__ half sQP[64 * ASTR];     // Q (prologue) then P [r][c]
    __shared__ half sK[2][64 * ASTR];   // [c][d]
    __shared__ half sV[2][64 * ASTR];   // [c][d]

    const int t = threadIdx.x, lane = t & 31, warp = t >> 5;
    const int g = lane >> 2, tig = lane & 3;
    const int qt = gridDim.x - 1 - blockIdx.x;  // long tiles first
    const int h = blockIdx.y, b = blockIdx.z;
    const int kvh = h >> 2;

    const size_t qbase = (size_t)b * TSEQ * HID + (size_t)h * HD;
    const half* kvp = kv + (size_t)b * TSEQ * KVW + (size_t)kvh * HD;

    const int kv_c = t >> 3, kv_ch = t & 7;

    auto issueKV = [&](int kt, int s) {
        #pragma unroll
        for (int u = 0; u < 4; u++) {
            int c = kv_c + u * 16;
            const half* rowp = kvp + (size_t)(kt * 64 + c) * KVW;
            cpa16(sptr(&sK[s][c * ASTR + kv_ch * 8]), rowp + kv_ch * 8);
            cpa16(sptr(&sV[s][c * ASTR + kv_ch * 8]), rowp + 256 + kv_ch * 8);
        }
        cp_commit();
    };

    issueKV(0, 0);

    // Q tile (pre-scaled by 1/8) -> sQP
    const half2 sc = __float2half2_rn(0.125f);
    #pragma unroll
    for (int u = 0; u < 4; u++) {
        int id = t + 128 * u;
        int r = id >> 3, dq = id & 7;
        uint4 v = *(const uint4*)(q + qbase + (size_t)(qt * 64 + r) * HID + dq * 8);
        half2* hv = (half2*)&v;
        #pragma unroll
        for (int i = 0; i < 4; i++) hv[i] = __hmul2(hv[i], sc);
        *(uint4*)&sQP[r * ASTR + dq * 8] = v;
    }
    cp_wait<0>();
    __syncthreads();

    // Q fragments to registers (sQP free after this)
    unsigned qa[4][4];
    {
        int row = warp * 16 + (lane & 15);
        int cb = (lane >> 4) * 8;
        #pragma unroll
        for (int ks = 0; ks < 4; ks++)
            ldsm4(qa[ks], sptr(&sQP[row * ASTR + ks * 16 + cb]));
    }

    float mr0 = -INFINITY, mr1 = -INFINITY, l0 = 0.f, l1 = 0.f;
    float O[8][4] = {};

    for (int kt = 0; kt <= qt; kt++) {
        int cur = kt & 1;
        if (kt < qt) issueKV(kt + 1, cur ^ 1);

        // S = Q K^T (warp: 16 x 64)
        float s[8][4] = {};
        #pragma unroll
        for (int ks = 0; ks < 4; ks++) {
            #pragma unroll
            for (int nf = 0; nf < 8; nf++) {
                unsigned bf[2];
                ldsm2(bf, sptr(&sK[cur][(nf * 8 + (lane & 7)) * ASTR
                                        + ks * 16 + ((lane >> 3) & 1) * 8]));
                mma16(s[nf], qa[ks], bf);
            }
        }

        // causal mask (diagonal tile only)
        if (kt == qt) {
            int r0 = qt * 64 + warp * 16 + g;
            #pragma unroll
            for (int nf = 0; nf < 8; nf++) {
                int col = kt * 64 + nf * 8 + tig * 2;
                if (col     > r0)     s[nf][0] = -INFINITY;
                if (col + 1 > r0)     s[nf][1] = -INFINITY;
                if (col     > r0 + 8) s[nf][2] = -INFINITY;
                if (col + 1 > r0 + 8) s[nf][3] = -INFINITY;
            }
        }

        // online softmax
        float mx0 = -INFINITY, mx1 = -INFINITY;
        #pragma unroll
        for (int nf = 0; nf < 8; nf++) {
            mx0 = fmaxf(mx0, fmaxf(s[nf][0], s[nf][1]));
            mx1 = fmaxf(mx1, fmaxf(s[nf][2], s[nf][3]));
        }
        #pragma unroll
        for (int off = 1; off < 4; off <<= 1) {
            mx0 = fmaxf(mx0, __shfl_xor_sync(0xffffffffu, mx0, off));
            mx1 = fmaxf(mx1, __shfl_xor_sync(0xffffffffu, mx1, off));
        }
        float nm0 = fmaxf(mr0, mx0), nm1 = fmaxf(mr1, mx1);
        float a0 = __expf(mr0 - nm0), a1 = __expf(mr1 - nm1);
        float rs0 = 0.f, rs1 = 0.f;
        #pragma unroll
        for (int nf = 0; nf < 8; nf++) {
            s[nf][0] = __expf(s[nf][0] - nm0);
            s[nf][1] = __expf(s[nf][1] - nm0);
            s[nf][2] = __expf(s[nf][2] - nm1);
            s[nf][3] = __expf(s[nf][3] - nm1);
            rs0 += s[nf][0] + s[nf][1];
            rs1 += s[nf][2] + s[nf][3];
        }
        #pragma unroll
        for (int off = 1; off < 4; off <<= 1) {
            rs0 += __shfl_xor_sync(0xffffffffu, rs0, off);
            rs1 += __shfl_xor_sync(0xffffffffu, rs1, off);
        }
        l0 = l0 * a0 + rs0;  l1 = l1 * a1 + rs1;
        mr0 = nm0;           mr1 = nm1;
        #pragma unroll
        for (int df = 0; df < 8; df++) {
            O[df][0] *= a0; O[df][1] *= a0;
            O[df][2] *= a1; O[df][3] *= a1;
        }

        // P -> sQP (warp-private rows)
        {
            int r = warp * 16 + g;
            #pragma unroll
            for (int nf = 0; nf < 8; nf++) {
                int c = nf * 8 + tig * 2;
                *(unsigned*)&sQP[r * ASTR + c]       = f2h2(s[nf][0], s[nf][1]);
                *(unsigned*)&sQP[(r + 8) * ASTR + c] = f2h2(s[nf][2], s[nf][3]);
            }
        }
        __syncwarp();

        // O += P @ V
        #pragma unroll
        for (int ks = 0; ks < 4; ks++) {
            unsigned pa[4];
            int row = warp * 16 + (lane & 15);
            int cb = ks * 16 + (lane >> 4) * 8;
            ldsm4(pa, sptr(&sQP[row * ASTR + cb]));
            #pragma unroll
            for (int df = 0; df < 8; df++) {
                unsigned bf[2];
                ldsm2t(bf, sptr(&sV[cur][(ks * 16 + (lane & 15)) * ASTR + df * 8]));
                mma16(O[df], pa, bf);
            }
        }

        if (kt < qt) {
            cp_wait<0>();
            __syncthreads();
        }
    }

    // epilogue: half output for Wo GEMM
    float inv0 = 1.f / l0, inv1 = 1.f / l1;
    int r = qt * 64 + warp * 16 + g;
    #pragma unroll
    for (int df = 0; df < 8; df++) {
        int c = h * HD + df * 8 + tig * 2;
        *(unsigned*)&o[(size_t)(b * TSEQ + r) * HID + c] =
            f2h2(O[df][0] * inv0, O[df][1] * inv0);
        *(unsigned*)&o[(size_t)(b * TSEQ + r + 8) * HID + c] =
            f2h2(O[df][2] * inv1, O[df][3] * inv1);
    }
}

// ---------------------------------------------------------------------------
extern "C" void kernel_launch(void* const* d_in, const int* in_sizes, int n_in,
                              void* d_out, int out_size)
{
    const float* x   = (const float*)d_in[0];
    const float* Wq  = (const float*)d_in[1];
    const float* Wkv = (const float*)d_in[2];
    const float* Wo  = (const float*)d_in[3];
    float* out = (float*)d_out;

    half *xh, *wqh, *wkvh, *woh, *qh, *kvh, *atth;
    cudaGetSymbolAddress((void**)&xh,   g_xh);
    cudaGetSymbolAddress((void**)&wqh,  g_wqh);
    cudaGetSymbolAddress((void**)&wkvh, g_wkvh);
    cudaGetSymbolAddress((void**)&woh,  g_woh);
    cudaGetSymbolAddress((void**)&qh,   g_qh);
    cudaGetSymbolAddress((void**)&kvh,  g_kvh);
    cudaGetSymbolAddress((void**)&atth, g_atth);

    conv_all<<<(CNT + 255) / 256, 256>>>(
        (const float4*)x, (const float4*)Wq, (const float4*)Wkv, (const float4*)Wo,
        (uint2*)xh, (uint2*)wqh, (uint2*)wkvh, (uint2*)woh);

    gemm_qkv<<<dim3(24, BT / 128), 256>>>(xh, wqh, wkvh, qh, kvh);
    attn_h<<<dim3(TSEQ / 64, 16, 2), 128>>>(qh, kvh, atth);
    gemm_wo<<<dim3(HID / 64, BT / 128), 256>>>(atth, woh, out);
}

// round 13
// speedup vs baseline: 1.1459x; 1.0339x over previous
#include <cuda_runtime.h>
#include <cuda_fp16.h>
#include <math.h>

#define BT   4096
#define HID  1024
#define TSEQ 2048
#define KVW  512
#define HD   64

// fp16 scratch (device globals — no allocation allowed)
__device__ __align__(256) half g_xh[(size_t)BT * HID];
__device__ __align__(256) half g_wqh[(size_t)HID * HID];
__device__ __align__(256) half g_wkvh[(size_t)HID * KVW];
__device__ __align__(256) half g_woh[(size_t)HID * HID];
__device__ __align__(256) half g_qh[(size_t)BT * HID];
__device__ __align__(256) half g_kvh[(size_t)BT * KVW];
__device__ __align__(256) half g_atth[(size_t)BT * HID];

// ---------------------------------------------------------------------------
// helpers
// ---------------------------------------------------------------------------
__device__ __forceinline__ unsigned f2h2(float a, float b) {
    half2 h = __float22half2_rn(make_float2(a, b));
    return *(unsigned*)&h;
}
__device__ __forceinline__ void mma16(float* d, const unsigned* a, const unsigned* b) {
    asm volatile(
        "mma.sync.aligned.m16n8k16.row.col.f32.f16.f16.f32 "
        "{%0,%1,%2,%3},{%4,%5,%6,%7},{%8,%9},{%0,%1,%2,%3};\n"
        : "+f"(d[0]), "+f"(d[1]), "+f"(d[2]), "+f"(d[3])
        : "r"(a[0]), "r"(a[1]), "r"(a[2]), "r"(a[3]), "r"(b[0]), "r"(b[1]));
}
__device__ __forceinline__ void ldsm4(unsigned* r, unsigned addr) {
    asm volatile("ldmatrix.sync.aligned.m8n8.x4.shared.b16 {%0,%1,%2,%3}, [%4];"
                 : "=r"(r[0]), "=r"(r[1]), "=r"(r[2]), "=r"(r[3]) : "r"(addr));
}
__device__ __forceinline__ void ldsm2(unsigned* r, unsigned addr) {
    asm volatile("ldmatrix.sync.aligned.m8n8.x2.shared.b16 {%0,%1}, [%2];"
                 : "=r"(r[0]), "=r"(r[1]) : "r"(addr));
}
__device__ __forceinline__ void ldsm2t(unsigned* r, unsigned addr) {
    asm volatile("ldmatrix.sync.aligned.m8n8.x2.trans.shared.b16 {%0,%1}, [%2];"
                 : "=r"(r[0]), "=r"(r[1]) : "r"(addr));
}
__device__ __forceinline__ unsigned sptr(const void* p) {
    return (unsigned)__cvta_generic_to_shared(p);
}
__device__ __forceinline__ void cpa16(unsigned dst, const void* src) {
    asm volatile("cp.async.cg.shared.global [%0], [%1], 16;" :: "r"(dst), "l"(src));
}
__device__ __forceinline__ void cp_commit() {
    asm volatile("cp.async.commit_group;");
}
template<int N> __device__ __forceinline__ void cp_wait() {
    asm volatile("cp.async.wait_group %0;" :: "n"(N));
}

// ---------------------------------------------------------------------------
// fused fp32 -> fp16 convert for all 4 tensors (one launch)
// ---------------------------------------------------------------------------
#define CN0 (BT * HID / 4)     // x
#define CN1 (HID * HID / 4)    // Wq
#define CN2 (HID * KVW / 4)    // Wkv
#define CN3 (HID * HID / 4)    // Wo
#define CNT (CN0 + CN1 + CN2 + CN3)

__global__ __launch_bounds__(256) void conv_all(
    const float4* __restrict__ x,  const float4* __restrict__ wq,
    const float4* __restrict__ wkv, const float4* __restrict__ wo,
    uint2* __restrict__ xh, uint2* __restrict__ wqh,
    uint2* __restrict__ wkvh, uint2* __restrict__ woh)
{
    int i = blockIdx.x * 256 + threadIdx.x;
    const float4* src;
    uint2* dst;
    int j;
    if (i < CN0)                  { src = x;   dst = xh;   j = i; }
    else if (i < CN0 + CN1)       { src = wq;  dst = wqh;  j = i - CN0; }
    else if (i < CN0 + CN1 + CN2) { src = wkv; dst = wkvh; j = i - CN0 - CN1; }
    else if (i < CNT)             { src = wo;  dst = woh;  j = i - CN0 - CN1 - CN2; }
    else return;
    float4 v = src[j];
    dst[j] = make_uint2(f2h2(v.x, v.y), f2h2(v.z, v.w));
}

// ---------------------------------------------------------------------------
// fp16 GEMM, cp.async 3-stage (measured-best config).
// C[M,N] = A[M,K] @ B[K,N]. BM=128, BN=64, BK=32, 256 thr, 8 warps (4m x 2n).
// ---------------------------------------------------------------------------
#define GAS 40   // sA row stride (halves): 32 + 8 pad
#define GBS 72   // sB row stride (halves): 64 + 8 pad

template<bool HALF_OUT>
__device__ __forceinline__ void gemm_core(
    const half* __restrict__ A, const half* __restrict__ B,
    void* __restrict__ Cv, int m0, int n0, int N, int K,
    half* sA, half* sB)
{
    const int t = threadIdx.x, lane = t & 31, warp = t >> 5;
    const int wm = warp & 3, wn = warp >> 2;
    const int g = lane >> 2, tig = lane & 3;
    const int KT = K >> 5;

    const int a_row = t >> 2, a_ch = t & 3;
    const int b_row = t >> 3, b_ch = t & 7;

    auto issue = [&](int kt, int s) {
        int k0 = kt * 32;
        half* dA = sA + s * 128 * GAS;
        half* dB = sB + s * 32 * GBS;
        #pragma unroll
        for (int u = 0; u < 2; u++) {
            int row = a_row + u * 64;
            cpa16(sptr(&dA[row * GAS + a_ch * 8]),
                  A + (size_t)(m0 + row) * K + k0 + a_ch * 8);
        }
        cpa16(sptr(&dB[b_row * GBS + b_ch * 8]),
              B + (size_t)(k0 + b_row) * N + n0 + b_ch * 8);
        cp_commit();
    };

    float acc[2][4][4] = {};

    issue(0, 0);
    issue(1, 1);
    cp_wait<1>();
    __syncthreads();

    for (int kt = 0; kt < KT; kt++) {
        int cur = kt % 3;
        if (kt + 2 < KT) issue(kt + 2, (kt + 2) % 3);

        half* cA = sA + cur * 128 * GAS;
        half* cB = sB + cur * 32 * GBS;

        #pragma unroll
        for (int ks = 0; ks < 2; ks++) {
            unsigned af[2][4];
            #pragma unroll
            for (int mf = 0; mf < 2; mf++) {
                int row = wm * 32 + mf * 16 + (lane & 15);
                int col = ks * 16 + (lane >> 4) * 8;
                ldsm4(af[mf], sptr(&cA[row * GAS + col]));
            }
            #pragma unroll
            for (int nf = 0; nf < 4; nf++) {
                unsigned bf[2];
                ldsm2t(bf, sptr(&cB[(ks * 16 + (lane & 15)) * GBS
                                    + wn * 32 + nf * 8]));
                #pragma unroll
                for (int mf = 0; mf < 2; mf++)
                    mma16(acc[mf][nf], af[mf], bf);
            }
        }

        if (kt + 1 < KT) {
            if (kt + 2 < KT) cp_wait<1>(); else cp_wait<0>();
            __syncthreads();
        }
    }

    #pragma unroll
    for (int mf = 0; mf < 2; mf++)
        #pragma unroll
        for (int nf = 0; nf < 4; nf++) {
            int r = m0 + wm * 32 + mf * 16 + g;
            int c = n0 + wn * 32 + nf * 8 + tig * 2;
            if (HALF_OUT) {
                half* C = (half*)Cv;
                *(unsigned*)&C[(size_t)r * N + c] =
                    f2h2(acc[mf][nf][0], acc[mf][nf][1]);
                *(unsigned*)&C[(size_t)(r + 8) * N + c] =
                    f2h2(acc[mf][nf][2], acc[mf][nf][3]);
            } else {
                float* C = (float*)Cv;
                *(float2*)(C + (size_t)r * N + c) =
                    make_float2(acc[mf][nf][0], acc[mf][nf][1]);
                *(float2*)(C + (size_t)(r + 8) * N + c) =
                    make_float2(acc[mf][nf][2], acc[mf][nf][3]);
            }
        }
}

// Fused Q + KV projection: blockIdx.x 0..15 -> Wq, 16..23 -> Wkv. half out.
__global__ __launch_bounds__(256) void gemm_qkv(
    const half* __restrict__ x,
    const half* __restrict__ Wq, const half* __restrict__ Wkv,
    half* __restrict__ q, half* __restrict__ kvo)
{
    __shared__ half sA[3 * 128 * GAS];
    __shared__ half sB[3 * 32 * GBS];
    int bx = blockIdx.x;
    if (bx < 16)
        gemm_core<true>(x, Wq, q, blockIdx.y * 128, bx * 64, HID, HID, sA, sB);
    else
        gemm_core<true>(x, Wkv, kvo, blockIdx.y * 128, (bx - 16) * 64, KVW, HID, sA, sB);
}

__global__ __launch_bounds__(256) void gemm_wo(
    const half* __restrict__ A, const half* __restrict__ B,
    float* __restrict__ C)
{
    __shared__ half sA[3 * 128 * GAS];
    __shared__ half sB[3 * 32 * GBS];
    gemm_core<false>(A, B, C, blockIdx.y * 128, blockIdx.x * 64, HID, HID, sA, sB);
}

// ---------------------------------------------------------------------------
// fp16 flash attention: 64-row q-tiles, 128 threads (4 warps), cp.async dbuf
// K/V. Grid (T/64, H, B). Warp w owns q-rows [w*16, w*16+16).
// FA2-style: P stays in registers — the S C-fragment IS the PV A-fragment.
// ---------------------------------------------------------------------------
#define ASTR 72   // 64 + 8 pad (144B rows)

__global__ __launch_bounds__(128) void attn_h(
    const half* __restrict__ q, const half* __restrict__ kv,
    half* __restrict__ o)
{
    __shared__ half sQ[64 * ASTR];      // Q (prologue only)
    __shared__ half sK[2][64 * ASTR];   // [c][d]
    __shared__ half sV[2][64 * ASTR];   // [c][d]

    const int t = threadIdx.x, lane = t & 31, warp = t >> 5;
    const int g = lane >> 2, tig = lane & 3;
    const int qt = gridDim.x - 1 - blockIdx.x;  // long tiles first
    const int h = blockIdx.y, b = blockIdx.z;
    const int kvh = h >> 2;

    const size_t qbase = (size_t)b * TSEQ * HID + (size_t)h * HD;
    const half* kvp = kv + (size_t)b * TSEQ * KVW + (size_t)kvh * HD;

    const int kv_c = t >> 3, kv_ch = t & 7;

    auto issueKV = [&](int kt, int s) {
        #pragma unroll
        for (int u = 0; u < 4; u++) {
            int c = kv_c + u * 16;
            const half* rowp = kvp + (size_t)(kt * 64 + c) * KVW;
            cpa16(sptr(&sK[s][c * ASTR + kv_ch * 8]), rowp + kv_ch * 8);
            cpa16(sptr(&sV[s][c * ASTR + kv_ch * 8]), rowp + 256 + kv_ch * 8);
        }
        cp_commit();
    };

    issueKV(0, 0);

    // Q tile (pre-scaled by 1/8) -> sQ
    const half2 sc = __float2half2_rn(0.125f);
    #pragma unroll
    for (int u = 0; u < 4; u++) {
        int id = t + 128 * u;
        int r = id >> 3, dq = id & 7;
        uint4 v = *(const uint4*)(q + qbase + (size_t)(qt * 64 + r) * HID + dq * 8);
        half2* hv = (half2*)&v;
        #pragma unroll
        for (int i = 0; i < 4; i++) hv[i] = __hmul2(hv[i], sc);
        *(uint4*)&sQ[r * ASTR + dq * 8] = v;
    }
    cp_wait<0>();
    __syncthreads();

    // Q fragments to registers
    unsigned qa[4][4];
    {
        int row = warp * 16 + (lane & 15);
        int cb = (lane >> 4) * 8;
        #pragma unroll
        for (int ks = 0; ks < 4; ks++)
            ldsm4(qa[ks], sptr(&sQ[row * ASTR + ks * 16 + cb]));
    }

    float mr0 = -INFINITY, mr1 = -INFINITY, l0 = 0.f, l1 = 0.f;
    float O[8][4] = {};

    for (int kt = 0; kt <= qt; kt++) {
        int cur = kt & 1;
        if (kt < qt) issueKV(kt + 1, cur ^ 1);

        // S = Q K^T (warp: 16 x 64)
        float s[8][4] = {};
        #pragma unroll
        for (int ks = 0; ks < 4; ks++) {
            #pragma unroll
            for (int nf = 0; nf < 8; nf++) {
                unsigned bf[2];
                ldsm2(bf, sptr(&sK[cur][(nf * 8 + (lane & 7)) * ASTR
                                        + ks * 16 + ((lane >> 3) & 1) * 8]));
                mma16(s[nf], qa[ks], bf);
            }
        }

        // causal mask (diagonal tile only)
        if (kt == qt) {
            int r0 = qt * 64 + warp * 16 + g;
            #pragma unroll
            for (int nf = 0; nf < 8; nf++) {
                int col = kt * 64 + nf * 8 + tig * 2;
                if (col     > r0)     s[nf][0] = -INFINITY;
                if (col + 1 > r0)     s[nf][1] = -INFINITY;
                if (col     > r0 + 8) s[nf][2] = -INFINITY;
                if (col + 1 > r0 + 8) s[nf][3] = -INFINITY;
            }
        }

        // online softmax
        float mx0 = -INFINITY, mx1 = -INFINITY;
        #pragma unroll
        for (int nf = 0; nf < 8; nf++) {
            mx0 = fmaxf(mx0, fmaxf(s[nf][0], s[nf][1]));
            mx1 = fmaxf(mx1, fmaxf(s[nf][2], s[nf][3]));
        }
        #pragma unroll
        for (int off = 1; off < 4; off <<= 1) {
            mx0 = fmaxf(mx0, __shfl_xor_sync(0xffffffffu, mx0, off));
            mx1 = fmaxf(mx1, __shfl_xor_sync(0xffffffffu, mx1, off));
        }
        float nm0 = fmaxf(mr0, mx0), nm1 = fmaxf(mr1, mx1);
        float a0 = __expf(mr0 - nm0), a1 = __expf(mr1 - nm1);
        float rs0 = 0.f, rs1 = 0.f;
        #pragma unroll
        for (int nf = 0; nf < 8; nf++) {
            s[nf][0] = __expf(s[nf][0] - nm0);
            s[nf][1] = __expf(s[nf][1] - nm0);
            s[nf][2] = __expf(s[nf][2] - nm1);
            s[nf][3] = __expf(s[nf][3] - nm1);
            rs0 += s[nf][0] + s[nf][1];
            rs1 += s[nf][2] + s[nf][3];
        }
        #pragma unroll
        for (int off = 1; off < 4; off <<= 1) {
            rs0 += __shfl_xor_sync(0xffffffffu, rs0, off);
            rs1 += __shfl_xor_sync(0xffffffffu, rs1, off);
        }
        l0 = l0 * a0 + rs0;  l1 = l1 * a1 + rs1;
        mr0 = nm0;           mr1 = nm1;
        #pragma unroll
        for (int df = 0; df < 8; df++) {
            O[df][0] *= a0; O[df][1] *= a0;
            O[df][2] *= a1; O[df][3] *= a1;
        }

        // O += P @ V — P directly from S registers (C-frag == A-frag layout):
        // a0=(g, ks*16+2tig)=s[2ks][0..1], a1=(g+8,·)=s[2ks][2..3],
        // a2=(g, ks*16+8+2tig)=s[2ks+1][0..1], a3=(g+8,·)=s[2ks+1][2..3].
        #pragma unroll
        for (int ks = 0; ks < 4; ks++) {
            unsigned pa[4];
            pa[0] = f2h2(s[2 * ks][0],     s[2 * ks][1]);
            pa[1] = f2h2(s[2 * ks][2],     s[2 * ks][3]);
            pa[2] = f2h2(s[2 * ks + 1][0], s[2 * ks + 1][1]);
            pa[3] = f2h2(s[2 * ks + 1][2], s[2 * ks + 1][3]);
            #pragma unroll
            for (int df = 0; df < 8; df++) {
                unsigned bf[2];
                ldsm2t(bf, sptr(&sV[cur][(ks * 16 + (lane & 15)) * ASTR + df * 8]));
                mma16(O[df], pa, bf);
            }
        }

        if (kt < qt) {
            cp_wait<0>();
            __syncthreads();
        }
    }

    // epilogue: half output for Wo GEMM
    float inv0 = 1.f / l0, inv1 = 1.f / l1;
    int r = qt * 64 + warp * 16 + g;
    #pragma unroll
    for (int df = 0; df < 8; df++) {
        int c = h * HD + df * 8 + tig * 2;
        *(unsigned*)&o[(size_t)(b * TSEQ + r) * HID + c] =
            f2h2(O[df][0] * inv0, O[df][1] * inv0);
        *(unsigned*)&o[(size_t)(b * TSEQ + r + 8) * HID + c] =
            f2h2(O[df][2] * inv1, O[df][3] * inv1);
    }
}

// ---------------------------------------------------------------------------
extern "C" void kernel_launch(void* const* d_in, const int* in_sizes, int n_in,
                              void* d_out, int out_size)
{
    const float* x   = (const float*)d_in[0];
    const float* Wq  = (const float*)d_in[1];
    const float* Wkv = (const float*)d_in[2];
    const float* Wo  = (const float*)d_in[3];
    float* out = (float*)d_out;

    half *xh, *wqh, *wkvh, *woh, *qh, *kvh, *atth;
    cudaGetSymbolAddress((void**)&xh,   g_xh);
    cudaGetSymbolAddress((void**)&wqh,  g_wqh);
    cudaGetSymbolAddress((void**)&wkvh, g_wkvh);
    cudaGetSymbolAddress((void**)&woh,  g_woh);
    cudaGetSymbolAddress((void**)&qh,   g_qh);
    cudaGetSymbolAddress((void**)&kvh,  g_kvh);
    cudaGetSymbolAddress((void**)&atth, g_atth);

    conv_all<<<(CNT + 255) / 256, 256>>>(
        (const float4*)x, (const float4*)Wq, (const float4*)Wkv, (const float4*)Wo,
        (uint2*)xh, (uint2*)wqh, (uint2*)wkvh, (uint2*)woh);

    gemm_qkv<<<dim3(24, BT / 128), 256>>>(xh, wqh, wkvh, qh, kvh);
    attn_h<<<dim3(TSEQ / 64, 16, 2), 128>>>(qh, kvh, atth);
    gemm_wo<<<dim3(HID / 64, BT / 128), 256>>>(atth, woh, out);
}

// round 14
// speedup vs baseline: 1.2163x; 1.0614x over previous
#include <cuda_runtime.h>
#include <cuda_fp16.h>
#include <math.h>

#define BT   4096
#define HID  1024
#define TSEQ 2048
#define KVW  512
#define HD   64

// fp16 scratch (device globals — no allocation allowed)
__device__ __align__(256) half g_xh[(size_t)BT * HID];
__device__ __align__(256) half g_wqh[(size_t)HID * HID];
__device__ __align__(256) half g_wkvh[(size_t)HID * KVW];
__device__ __align__(256) half g_woh[(size_t)HID * HID];
__device__ __align__(256) half g_qh[(size_t)BT * HID];
__device__ __align__(256) half g_kvh[(size_t)BT * KVW];
__device__ __align__(256) half g_atth[(size_t)BT * HID];

// ---------------------------------------------------------------------------
// helpers
// ---------------------------------------------------------------------------
__device__ __forceinline__ unsigned f2h2(float a, float b) {
    half2 h = __float22half2_rn(make_float2(a, b));
    return *(unsigned*)&h;
}
__device__ __forceinline__ void mma16(float* d, const unsigned* a, const unsigned* b) {
    asm volatile(
        "mma.sync.aligned.m16n8k16.row.col.f32.f16.f16.f32 "
        "{%0,%1,%2,%3},{%4,%5,%6,%7},{%8,%9},{%0,%1,%2,%3};\n"
        : "+f"(d[0]), "+f"(d[1]), "+f"(d[2]), "+f"(d[3])
        : "r"(a[0]), "r"(a[1]), "r"(a[2]), "r"(a[3]), "r"(b[0]), "r"(b[1]));
}
__device__ __forceinline__ void ldsm4(unsigned* r, unsigned addr) {
    asm volatile("ldmatrix.sync.aligned.m8n8.x4.shared.b16 {%0,%1,%2,%3}, [%4];"
                 : "=r"(r[0]), "=r"(r[1]), "=r"(r[2]), "=r"(r[3]) : "r"(addr));
}
__device__ __forceinline__ void ldsm4t(unsigned* r, unsigned addr) {
    asm volatile("ldmatrix.sync.aligned.m8n8.x4.trans.shared.b16 {%0,%1,%2,%3}, [%4];"
                 : "=r"(r[0]), "=r"(r[1]), "=r"(r[2]), "=r"(r[3]) : "r"(addr));
}
__device__ __forceinline__ unsigned sptr(const void* p) {
    return (unsigned)__cvta_generic_to_shared(p);
}
__device__ __forceinline__ void cpa16(unsigned dst, const void* src) {
    asm volatile("cp.async.cg.shared.global [%0], [%1], 16;" :: "r"(dst), "l"(src));
}
__device__ __forceinline__ void cp_commit() {
    asm volatile("cp.async.commit_group;");
}
template<int N> __device__ __forceinline__ void cp_wait() {
    asm volatile("cp.async.wait_group %0;" :: "n"(N));
}

// ---------------------------------------------------------------------------
// fused fp32 -> fp16 convert for all 4 tensors (one launch)
// ---------------------------------------------------------------------------
#define CN0 (BT * HID / 4)     // x
#define CN1 (HID * HID / 4)    // Wq
#define CN2 (HID * KVW / 4)    // Wkv
#define CN3 (HID * HID / 4)    // Wo
#define CNT (CN0 + CN1 + CN2 + CN3)

__global__ __launch_bounds__(256) void conv_all(
    const float4* __restrict__ x,  const float4* __restrict__ wq,
    const float4* __restrict__ wkv, const float4* __restrict__ wo,
    uint2* __restrict__ xh, uint2* __restrict__ wqh,
    uint2* __restrict__ wkvh, uint2* __restrict__ woh)
{
    int i = blockIdx.x * 256 + threadIdx.x;
    const float4* src;
    uint2* dst;
    int j;
    if (i < CN0)                  { src = x;   dst = xh;   j = i; }
    else if (i < CN0 + CN1)       { src = wq;  dst = wqh;  j = i - CN0; }
    else if (i < CN0 + CN1 + CN2) { src = wkv; dst = wkvh; j = i - CN0 - CN1; }
    else if (i < CNT)             { src = wo;  dst = woh;  j = i - CN0 - CN1 - CN2; }
    else return;
    float4 v = src[j];
    dst[j] = make_uint2(f2h2(v.x, v.y), f2h2(v.z, v.w));
}

// ---------------------------------------------------------------------------
// fp16 GEMM, cp.async 2-stage, BK=64 (halved iteration/sync count).
// C[M,N] = A[M,K] @ B[K,N]. BM=128, BN=64, BK=64, 256 thr, 8 warps (4m x 2n).
// ---------------------------------------------------------------------------
#define GAS 72   // sA row stride (halves): 64 + 8 pad (144B rows)
#define GBS 72   // sB row stride (halves): 64 + 8 pad
#define SA_ST (128 * GAS)
#define SB_ST (64 * GBS)
#define GSMEM ((2 * (SA_ST + SB_ST)) * 2)   // bytes

template<bool HALF_OUT>
__device__ __forceinline__ void gemm_core(
    const half* __restrict__ A, const half* __restrict__ B,
    void* __restrict__ Cv, int m0, int n0, int N, int K,
    half* sA, half* sB)
{
    const int t = threadIdx.x, lane = t & 31, warp = t >> 5;
    const int wm = warp & 3, wn = warp >> 2;
    const int g = lane >> 2, tig = lane & 3;
    const int KT = K >> 6;

    const int ld_row = t >> 3, ld_ch = t & 7;   // 8 chunks (of 8 halves) per row

    auto issue = [&](int kt, int s) {
        int k0 = kt * 64;
        half* dA = sA + s * SA_ST;
        half* dB = sB + s * SB_ST;
        #pragma unroll
        for (int u = 0; u < 4; u++) {            // A: 128 rows x 64 halves
            int row = ld_row + u * 32;
            cpa16(sptr(&dA[row * GAS + ld_ch * 8]),
                  A + (size_t)(m0 + row) * K + k0 + ld_ch * 8);
        }
        #pragma unroll
        for (int u = 0; u < 2; u++) {            // B: 64 rows x 64 halves
            int row = ld_row + u * 32;
            cpa16(sptr(&dB[row * GBS + ld_ch * 8]),
                  B + (size_t)(k0 + row) * N + n0 + ld_ch * 8);
        }
        cp_commit();
    };

    float acc[2][4][4] = {};

    issue(0, 0);
    cp_wait<0>();
    __syncthreads();

    for (int kt = 0; kt < KT; kt++) {
        int cur = kt & 1;
        if (kt + 1 < KT) issue(kt + 1, cur ^ 1);

        half* cA = sA + cur * SA_ST;
        half* cB = sB + cur * SB_ST;

        #pragma unroll
        for (int ks = 0; ks < 4; ks++) {
            unsigned af[2][4];
            #pragma unroll
            for (int mf = 0; mf < 2; mf++) {
                int row = wm * 32 + mf * 16 + (lane & 15);
                int col = ks * 16 + (lane >> 4) * 8;
                ldsm4(af[mf], sptr(&cA[row * GAS + col]));
            }
            #pragma unroll
            for (int nfp = 0; nfp < 2; nfp++) {
                // paired B frags (nf=2*nfp, 2*nfp+1) via one ldsm4t
                unsigned bf[4];
                int mat = lane >> 3;
                int kr = ks * 16 + (mat & 1) * 8 + (lane & 7);
                int cc = wn * 32 + nfp * 16 + (mat >> 1) * 8;
                ldsm4t(bf, sptr(&cB[kr * GBS + cc]));
                #pragma unroll
                for (int mf = 0; mf < 2; mf++) {
                    mma16(acc[mf][2 * nfp],     af[mf], bf);
                    mma16(acc[mf][2 * nfp + 1], af[mf], bf + 2);
                }
            }
        }

        if (kt + 1 < KT) {
            cp_wait<0>();
            __syncthreads();
        }
    }

    #pragma unroll
    for (int mf = 0; mf < 2; mf++)
        #pragma unroll
        for (int nf = 0; nf < 4; nf++) {
            int r = m0 + wm * 32 + mf * 16 + g;
            int c = n0 + wn * 32 + nf * 8 + tig * 2;
            if (HALF_OUT) {
                half* C = (half*)Cv;
                *(unsigned*)&C[(size_t)r * N + c] =
                    f2h2(acc[mf][nf][0], acc[mf][nf][1]);
                *(unsigned*)&C[(size_t)(r + 8) * N + c] =
                    f2h2(acc[mf][nf][2], acc[mf][nf][3]);
            } else {
                float* C = (float*)Cv;
                *(float2*)(C + (size_t)r * N + c) =
                    make_float2(acc[mf][nf][0], acc[mf][nf][1]);
                *(float2*)(C + (size_t)(r + 8) * N + c) =
                    make_float2(acc[mf][nf][2], acc[mf][nf][3]);
            }
        }
}

// Fused Q + KV projection: blockIdx.x 0..15 -> Wq, 16..23 -> Wkv. half out.
__global__ __launch_bounds__(256) void gemm_qkv(
    const half* __restrict__ x,
    const half* __restrict__ Wq, const half* __restrict__ Wkv,
    half* __restrict__ q, half* __restrict__ kvo)
{
    extern __shared__ half dsm[];
    half* sA = dsm;
    half* sB = dsm + 2 * SA_ST;
    int bx = blockIdx.x;
    if (bx < 16)
        gemm_core<true>(x, Wq, q, blockIdx.y * 128, bx * 64, HID, HID, sA, sB);
    else
        gemm_core<true>(x, Wkv, kvo, blockIdx.y * 128, (bx - 16) * 64, KVW, HID, sA, sB);
}

__global__ __launch_bounds__(256) void gemm_wo(
    const half* __restrict__ A, const half* __restrict__ B,
    float* __restrict__ C)
{
    extern __shared__ half dsm[];
    half* sA = dsm;
    half* sB = dsm + 2 * SA_ST;
    gemm_core<false>(A, B, C, blockIdx.y * 128, blockIdx.x * 64, HID, HID, sA, sB);
}

// ---------------------------------------------------------------------------
// fp16 flash attention: 64-row q-tiles, 128 threads (4 warps), cp.async dbuf
// K/V. Grid (T/64, H, B). Warp w owns q-rows [w*16, w*16+16).
// FA2-style register-P; paired ldsm4/ldsm4t for K and V fragments.
// ---------------------------------------------------------------------------
#define ASTR 72   // 64 + 8 pad (144B rows)

__global__ __launch_bounds__(128) void attn_h(
    const half* __restrict__ q, const half* __restrict__ kv,
    half* __restrict__ o)
{
    __shared__ half sQ[64 * ASTR];      // Q (prologue only)
    __shared__ half sK[2][64 * ASTR];   // [c][d]
    __shared__ half sV[2][64 * ASTR];   // [c][d]

    const int t = threadIdx.x, lane = t & 31, warp = t >> 5;
    const int g = lane >> 2, tig = lane & 3;
    const int qt = gridDim.x - 1 - blockIdx.x;  // long tiles first
    const int h = blockIdx.y, b = blockIdx.z;
    const int kvh = h >> 2;

    const size_t qbase = (size_t)b * TSEQ * HID + (size_t)h * HD;
    const half* kvp = kv + (size_t)b * TSEQ * KVW + (size_t)kvh * HD;

    const int kv_c = t >> 3, kv_ch = t & 7;

    auto issueKV = [&](int kt, int s) {
        #pragma unroll
        for (int u = 0; u < 4; u++) {
            int c = kv_c + u * 16;
            const half* rowp = kvp + (size_t)(kt * 64 + c) * KVW;
            cpa16(sptr(&sK[s][c * ASTR + kv_ch * 8]), rowp + kv_ch * 8);
            cpa16(sptr(&sV[s][c * ASTR + kv_ch * 8]), rowp + 256 + kv_ch * 8);
        }
        cp_commit();
    };

    issueKV(0, 0);

    // Q tile (pre-scaled by 1/8) -> sQ
    const half2 sc = __float2half2_rn(0.125f);
    #pragma unroll
    for (int u = 0; u < 4; u++) {
        int id = t + 128 * u;
        int r = id >> 3, dq = id & 7;
        uint4 v = *(const uint4*)(q + qbase + (size_t)(qt * 64 + r) * HID + dq * 8);
        half2* hv = (half2*)&v;
        #pragma unroll
        for (int i = 0; i < 4; i++) hv[i] = __hmul2(hv[i], sc);
        *(uint4*)&sQ[r * ASTR + dq * 8] = v;
    }
    cp_wait<0>();
    __syncthreads();

    // Q fragments to registers
    unsigned qa[4][4];
    {
        int row = warp * 16 + (lane & 15);
        int cb = (lane >> 4) * 8;
        #pragma unroll
        for (int ks = 0; ks < 4; ks++)
            ldsm4(qa[ks], sptr(&sQ[row * ASTR + ks * 16 + cb]));
    }

    float mr0 = -INFINITY, mr1 = -INFINITY, l0 = 0.f, l1 = 0.f;
    float O[8][4] = {};

    for (int kt = 0; kt <= qt; kt++) {
        int cur = kt & 1;
        if (kt < qt) issueKV(kt + 1, cur ^ 1);

        // S = Q K^T (warp: 16 x 64) — paired K frags via ldsm4
        float s[8][4] = {};
        #pragma unroll
        for (int ks = 0; ks < 4; ks++) {
            #pragma unroll
            for (int nfp = 0; nfp < 4; nfp++) {
                unsigned bf[4];
                int mat = lane >> 3;
                int rr = nfp * 16 + (mat >> 1) * 8 + (lane & 7);
                int cc = ks * 16 + (mat & 1) * 8;
                ldsm4(bf, sptr(&sK[cur][rr * ASTR + cc]));
                mma16(s[2 * nfp],     qa[ks], bf);
                mma16(s[2 * nfp + 1], qa[ks], bf + 2);
            }
        }

        // causal mask (diagonal tile only)
        if (kt == qt) {
            int r0 = qt * 64 + warp * 16 + g;
            #pragma unroll
            for (int nf = 0; nf < 8; nf++) {
                int col = kt * 64 + nf * 8 + tig * 2;
                if (col     > r0)     s[nf][0] = -INFINITY;
                if (col + 1 > r0)     s[nf][1] = -INFINITY;
                if (col     > r0 + 8) s[nf][2] = -INFINITY;
                if (col + 1 > r0 + 8) s[nf][3] = -INFINITY;
            }
        }

        // online softmax
        float mx0 = -INFINITY, mx1 = -INFINITY;
        #pragma unroll
        for (int nf = 0; nf < 8; nf++) {
            mx0 = fmaxf(mx0, fmaxf(s[nf][0], s[nf][1]));
            mx1 = fmaxf(mx1, fmaxf(s[nf][2], s[nf][3]));
        }
        #pragma unroll
        for (int off = 1; off < 4; off <<= 1) {
            mx0 = fmaxf(mx0, __shfl_xor_sync(0xffffffffu, mx0, off));
            mx1 = fmaxf(mx1, __shfl_xor_sync(0xffffffffu, mx1, off));
        }
        float nm0 = fmaxf(mr0, mx0), nm1 = fmaxf(mr1, mx1);
        float a0 = __expf(mr0 - nm0), a1 = __expf(mr1 - nm1);
        float rs0 = 0.f, rs1 = 0.f;
        #pragma unroll
        for (int nf = 0; nf < 8; nf++) {
            s[nf][0] = __expf(s[nf][0] - nm0);
            s[nf][1] = __expf(s[nf][1] - nm0);
            s[nf][2] = __expf(s[nf][2] - nm1);
            s[nf][3] = __expf(s[nf][3] - nm1);
            rs0 += s[nf][0] + s[nf][1];
            rs1 += s[nf][2] + s[nf][3];
        }
        #pragma unroll
        for (int off = 1; off < 4; off <<= 1) {
            rs0 += __shfl_xor_sync(0xffffffffu, rs0, off);
            rs1 += __shfl_xor_sync(0xffffffffu, rs1, off);
        }
        l0 = l0 * a0 + rs0;  l1 = l1 * a1 + rs1;
        mr0 = nm0;           mr1 = nm1;
        #pragma unroll
        for (int df = 0; df < 8; df++) {
            O[df][0] *= a0; O[df][1] *= a0;
            O[df][2] *= a1; O[df][3] *= a1;
        }

        // O += P @ V — P from S registers (C-frag == A-frag layout);
        // paired V frags via ldsm4t.
        #pragma unroll
        for (int ks = 0; ks < 4; ks++) {
            unsigned pa[4];
            pa[0] = f2h2(s[2 * ks][0],     s[2 * ks][1]);
            pa[1] = f2h2(s[2 * ks][2],     s[2 * ks][3]);
            pa[2] = f2h2(s[2 * ks + 1][0], s[2 * ks + 1][1]);
            pa[3] = f2h2(s[2 * ks + 1][2], s[2 * ks + 1][3]);
            #pragma unroll
            for (int dfp = 0; dfp < 4; dfp++) {
                unsigned bf[4];
                int mat = lane >> 3;
                int kr = ks * 16 + (mat & 1) * 8 + (lane & 7);
                int cc = dfp * 16 + (mat >> 1) * 8;
                ldsm4t(bf, sptr(&sV[cur][kr * ASTR + cc]));
                mma16(O[2 * dfp],     pa, bf);
                mma16(O[2 * dfp + 1], pa, bf + 2);
            }
        }

        if (kt < qt) {
            cp_wait<0>();
            __syncthreads();
        }
    }

    // epilogue: half output for Wo GEMM
    float inv0 = 1.f / l0, inv1 = 1.f / l1;
    int r = qt * 64 + warp * 16 + g;
    #pragma unroll
    for (int df = 0; df < 8; df++) {
        int c = h * HD + df * 8 + tig * 2;
        *(unsigned*)&o[(size_t)(b * TSEQ + r) * HID + c] =
            f2h2(O[df][0] * inv0, O[df][1] * inv0);
        *(unsigned*)&o[(size_t)(b * TSEQ + r + 8) * HID + c] =
            f2h2(O[df][2] * inv1, O[df][3] * inv1);
    }
}

// ---------------------------------------------------------------------------
extern "C" void kernel_launch(void* const* d_in, const int* in_sizes, int n_in,
                              void* d_out, int out_size)
{
    const float* x   = (const float*)d_in[0];
    const float* Wq  = (const float*)d_in[1];
    const float* Wkv = (const float*)d_in[2];
    const float* Wo  = (const float*)d_in[3];
    float* out = (float*)d_out;

    half *xh, *wqh, *wkvh, *woh, *qh, *kvh, *atth;
    cudaGetSymbolAddress((void**)&xh,   g_xh);
    cudaGetSymbolAddress((void**)&wqh,  g_wqh);
    cudaGetSymbolAddress((void**)&wkvh, g_wkvh);
    cudaGetSymbolAddress((void**)&woh,  g_woh);
    cudaGetSymbolAddress((void**)&qh,   g_qh);
    cudaGetSymbolAddress((void**)&kvh,  g_kvh);
    cudaGetSymbolAddress((void**)&atth, g_atth);

    cudaFuncSetAttribute(gemm_qkv,
                         cudaFuncAttributeMaxDynamicSharedMemorySize, GSMEM);
    cudaFuncSetAttribute(gemm_wo,
                         cudaFuncAttributeMaxDynamicSharedMemorySize, GSMEM);

    conv_all<<<(CNT + 255) / 256, 256>>>(
        (const float4*)x, (const float4*)Wq, (const float4*)Wkv, (const float4*)Wo,
        (uint2*)xh, (uint2*)wqh, (uint2*)wkvh, (uint2*)woh);

    gemm_qkv<<<dim3(24, BT / 128), 256, GSMEM>>>(xh, wqh, wkvh, qh, kvh);
    attn_h<<<dim3(TSEQ / 64, 16, 2), 128>>>(qh, kvh, atth);
    gemm_wo<<<dim3(HID / 64, BT / 128), 256, GSMEM>>>(atth, woh, out);
}